// round 13
// baseline (speedup 1.0000x reference)
#include <cuda_runtime.h>
#include <cuda_fp16.h>
#include <cstdint>

// ---------------- problem constants ----------------
#define BATCH   16384
#define SEQ     4
#define DIM     512
#define ROWS    (BATCH * SEQ)      // 65536
#define HEADS   8
#define GAMMA_F 0.4f
#define SCALE_F 0.044194173824159216f  // 512^-0.5

// scratch (allocation-free rule)
__device__ __half g_Qh [ROWS * DIM];          // fp16 Q
__device__ __half g_KVh[ROWS * 2 * DIM];      // fp16 KV
__device__ __half g_AOh[ROWS * DIM];          // fp16 attention output
__device__ __half g_Xh [ROWS * DIM];          // fp16 x
__device__ __half g_Ch [ROWS * DIM];          // fp16 context
// pre-transposed fp16 weights: Wt[n][k]
__device__ __half g_WtQh [DIM * DIM];
__device__ __half g_WtKVh[2 * DIM * DIM];
__device__ __half g_WtOh [DIM * DIM];

// ---------------- GEMM tiling ----------------
#define BM 128
#define BN 128
#define BK 64                       // 64 fp16 = 128B rows
#define NKT (DIM / BK)              // 8
#define W_STAGE 16384
#define X_STAGE 16384
#define STAGE_BYTES (W_STAGE + X_STAGE)
#define SMEM_BYTES (2 * STAGE_BYTES)   // 65536 -> 3 CTA/SM (192KB)

// ---------------- helpers ----------------
__device__ __forceinline__ uint32_t smem_u32(const void* p) {
    uint32_t a;
    asm("{ .reg .u64 t; cvta.to.shared.u64 t, %1; cvt.u32.u64 %0, t; }"
        : "=r"(a) : "l"(p));
    return a;
}
__device__ __forceinline__ void cp16(uint32_t dst, const void* src) {
    asm volatile("cp.async.cg.shared.global [%0], [%1], 16;"
                 :: "r"(dst), "l"(src));
}
__device__ __forceinline__ void cp_commit() {
    asm volatile("cp.async.commit_group;");
}
template <int N>
__device__ __forceinline__ void cp_wait() {
    asm volatile("cp.async.wait_group %0;" :: "n"(N));
}
#define LDSM4(r0, r1, r2, r3, a) \
    asm volatile("ldmatrix.sync.aligned.m8n8.x4.shared.b16 {%0,%1,%2,%3}, [%4];" \
        : "=r"(r0), "=r"(r1), "=r"(r2), "=r"(r3) : "r"(a))

__device__ __forceinline__ void mma_f16(
    float c[4], uint32_t a0, uint32_t a1, uint32_t a2, uint32_t a3,
    uint32_t b0, uint32_t b1)
{
    asm volatile(
        "mma.sync.aligned.m16n8k16.row.col.f32.f16.f16.f32 "
        "{%0,%1,%2,%3}, {%4,%5,%6,%7}, {%8,%9}, {%0,%1,%2,%3};"
        : "+f"(c[0]), "+f"(c[1]), "+f"(c[2]), "+f"(c[3])
        : "r"(a0), "r"(a1), "r"(a2), "r"(a3), "r"(b0), "r"(b1));
}

// unpack 8 halves (uint4) -> 8 floats
__device__ __forceinline__ void cvt8(const uint4& u, float* f) {
    float2 a = __half22float2(*(const __half2*)&u.x);
    float2 b = __half22float2(*(const __half2*)&u.y);
    float2 c = __half22float2(*(const __half2*)&u.z);
    float2 d = __half22float2(*(const __half2*)&u.w);
    f[0] = a.x; f[1] = a.y; f[2] = b.x; f[3] = b.y;
    f[4] = c.x; f[5] = c.y; f[6] = d.x; f[7] = d.y;
}

// ---------------- prep: all 3 weights transposed+rounded in ONE launch ----------------
__global__ void transpose_all(const float* __restrict__ Wq,
                              const float* __restrict__ Wkv,
                              const float* __restrict__ Wo)
{
    int y = blockIdx.y;
    const float* W;
    __half* Wt;
    int N, n0;
    if (y < 16)      { W = Wq;  Wt = g_WtQh;  N = DIM;     n0 = y * 32; }
    else if (y < 48) { W = Wkv; Wt = g_WtKVh; N = 2 * DIM; n0 = (y - 16) * 32; }
    else             { W = Wo;  Wt = g_WtOh;  N = DIM;     n0 = (y - 48) * 32; }

    __shared__ float t[32][33];
    int k0 = blockIdx.x * 32;
    int tx = threadIdx.x, ty = threadIdx.y;
#pragma unroll
    for (int i = ty; i < 32; i += 8)
        t[i][tx] = W[(size_t)(k0 + i) * N + n0 + tx];
    __syncthreads();
#pragma unroll
    for (int i = ty; i < 32; i += 8)
        Wt[(size_t)(n0 + i) * DIM + k0 + tx] = __float2half_rn(t[tx][i]);
}

// ---------------- prep: x AND ctx -> fp16 in ONE launch ----------------
#define TOH_BLOCKS (ROWS * DIM / 8 / 256)     // 16384 per tensor
__global__ void to_half2(const float* __restrict__ x, const float* __restrict__ ctx)
{
    int bid = blockIdx.x;
    const float* src;
    __half* dst;
    int base;
    if (bid < TOH_BLOCKS) { src = x;   dst = g_Xh; base = bid; }
    else                  { src = ctx; dst = g_Ch; base = bid - TOH_BLOCKS; }
    int i = (base * 256 + threadIdx.x) * 8;
    float4 v0 = __ldcs((const float4*)&src[i]);
    float4 v1 = __ldcs((const float4*)&src[i + 4]);
    __half2 h[4];
    h[0] = __floats2half2_rn(v0.x, v0.y);
    h[1] = __floats2half2_rn(v0.z, v0.w);
    h[2] = __floats2half2_rn(v1.x, v1.y);
    h[3] = __floats2half2_rn(v1.z, v1.w);
    *(uint4*)&dst[i] = *(uint4*)h;
}

// shared MMA mainloop body (one k-tile)
__device__ __forceinline__ void mma_tile(
    uint32_t sW, uint32_t sX, int nb, int mb,
    int lx7, int arow, int agb, int brow, int bgb,
    float acc[2][8][4])
{
#pragma unroll
    for (int ks = 0; ks < 4; ks++) {
        uint32_t aw[2][4];
#pragma unroll
        for (int inf = 0; inf < 2; inf++) {
            int row = nb + inf * 16 + arow;
            uint32_t ad = sW + row * 128
                        + (uint32_t)(((2 * ks + agb) ^ lx7) << 4);
            LDSM4(aw[inf][0], aw[inf][1], aw[inf][2], aw[inf][3], ad);
        }
        uint32_t bx[8][2];
#pragma unroll
        for (int jp = 0; jp < 4; jp++) {
            int row = mb + jp * 16 + brow;
            uint32_t ad = sX + row * 128
                        + (uint32_t)(((2 * ks + bgb) ^ lx7) << 4);
            uint32_t r0, r1, r2, r3;
            LDSM4(r0, r1, r2, r3, ad);
            bx[2 * jp][0]     = r0;
            bx[2 * jp][1]     = r1;
            bx[2 * jp + 1][0] = r2;
            bx[2 * jp + 1][1] = r3;
        }
#pragma unroll
        for (int inf = 0; inf < 2; inf++)
#pragma unroll
            for (int jm = 0; jm < 8; jm++)
                mma_f16(acc[inf][jm],
                        aw[inf][0], aw[inf][1], aw[inf][2], aw[inf][3],
                        bx[jm][0], bx[jm][1]);
    }
}

// ---------------- fused Q+KV GEMM (fp16 in, fp16 out), 2-stage / 3 CTA ----------------
// grid.x: 0..3 -> Q n-tiles (Xh @ WtQ), 4..11 -> KV n-tiles (Ch @ WtKV)
__global__ __launch_bounds__(256, 3) void gemm_qkv(
    const float* __restrict__ bq, const float* __restrict__ bkv)
{
    extern __shared__ float smf[];
    const uint32_t smb = smem_u32(smf);

    const int nt = blockIdx.x;
    const int isKV = (nt >= 4);
    const __half* Act  = isKV ? g_Ch : g_Xh;
    const __half* Wt   = isKV ? g_WtKVh : g_WtQh;
    const float* bias  = isKV ? bkv : bq;
    __half* Co         = isKV ? g_KVh : g_Qh;
    const int ldN      = isKV ? 2 * DIM : DIM;
    const int n0       = (isKV ? nt - 4 : nt) * BN;
    const int m0       = blockIdx.y * BM;

    const int tid = threadIdx.x;
    const int wid = tid >> 5;
    const int l   = tid & 31;
    const int nb = (wid & 3) * 32, mb = (wid >> 2) * 64;

    const int lx7  = l & 7;
    const int arow = (l & 7) + ((l >> 3) & 1) * 8;
    const int agb  = l >> 4;
    const int brow = (l & 7) + ((l >> 4) << 3);
    const int bgb  = (l >> 3) & 1;

    float acc[2][8][4];
#pragma unroll
    for (int i = 0; i < 2; i++)
#pragma unroll
        for (int j = 0; j < 8; j++)
#pragma unroll
            for (int c = 0; c < 4; c++) acc[i][j][c] = 0.0f;

    const int cr = tid >> 3, cc = tid & 7;
    const uint32_t coff = (uint32_t)(cr * 128 + ((cc ^ (cr & 7)) << 4));
    const __half* wsrc = &Wt[(size_t)(n0 + cr) * DIM + cc * 8];
    const __half* xsrc = &Act[(size_t)(m0 + cr) * DIM + cc * 8];

#define QKV_ISSUE(T) do {                                                   \
        uint32_t sW_ = smb + ((T) & 1) * STAGE_BYTES;                       \
        uint32_t sX_ = sW_ + W_STAGE;                                       \
        _Pragma("unroll")                                                   \
        for (int j = 0; j < 4; j++) {                                       \
            uint32_t o_ = coff + (uint32_t)(j * 32 * 128);                  \
            cp16(sW_ + o_, wsrc + (size_t)(j * 32) * DIM + (T) * BK);       \
            cp16(sX_ + o_, xsrc + (size_t)(j * 32) * DIM + (T) * BK);       \
        }                                                                   \
    } while (0)

    QKV_ISSUE(0); cp_commit();
    QKV_ISSUE(1); cp_commit();

#pragma unroll
    for (int kt = 0; kt < NKT; kt++) {
        cp_wait<1>();                  // tile kt landed (kt+1 may still fly)
        __syncthreads();
        uint32_t sW = smb + (kt & 1) * STAGE_BYTES;
        mma_tile(sW, sW + W_STAGE, nb, mb, lx7, arow, agb, brow, bgb, acc);
        __syncthreads();               // all warps done reading buf kt&1
        if (kt + 2 < NKT) { QKV_ISSUE(kt + 2); cp_commit(); }
    }
#undef QKV_ISSUE

    // epilogue: two 64-row passes through smem (fits 64KB), bias, fp16 store
    cp_wait<0>();
    float* Cs = smf;                   // [64 m][132 pitch] fp32 = 33.8KB
    const int gq = l >> 2, tq = l & 3;
#pragma unroll
    for (int half = 0; half < 2; half++) {
        __syncthreads();
        if ((wid >> 2) == half) {
#pragma unroll
            for (int inf = 0; inf < 2; inf++) {
                int nn = nb + inf * 16 + gq;
#pragma unroll
                for (int jm = 0; jm < 8; jm++) {
                    int mm = jm * 8 + 2 * tq;   // local row 0..63
                    Cs[mm * 132 + nn]           = acc[inf][jm][0];
                    Cs[(mm + 1) * 132 + nn]     = acc[inf][jm][1];
                    Cs[mm * 132 + nn + 8]       = acc[inf][jm][2];
                    Cs[(mm + 1) * 132 + nn + 8] = acc[inf][jm][3];
                }
            }
        }
        __syncthreads();
#pragma unroll
        for (int it = 0; it < 4; it++) {
            int idx = tid + it * 256;
            int r = idx >> 4, c = (idx & 15) * 8;
            float4 v0 = *(float4*)&Cs[r * 132 + c];
            float4 v1 = *(float4*)&Cs[r * 132 + c + 4];
            const float* bp = &bias[n0 + c];
            __half2 h[4];
            h[0] = __floats2half2_rn(v0.x + bp[0], v0.y + bp[1]);
            h[1] = __floats2half2_rn(v0.z + bp[2], v0.w + bp[3]);
            h[2] = __floats2half2_rn(v1.x + bp[4], v1.y + bp[5]);
            h[3] = __floats2half2_rn(v1.z + bp[6], v1.w + bp[7]);
            *(uint4*)&Co[(size_t)(m0 + half * 64 + r) * ldN + n0 + c] = *(uint4*)h;
        }
    }
}

// ---------------- O GEMM: fp16 AO in, fp32 out, 2-stage / 3 CTA ----------------
__global__ __launch_bounds__(256, 3) void gemm_o(
    const float* __restrict__ bias, float* __restrict__ Cext, int ldN)
{
    extern __shared__ float smf[];
    const uint32_t smb = smem_u32(smf);

    const int tid = threadIdx.x;
    const int wid = tid >> 5;
    const int l   = tid & 31;
    const int nb = (wid & 3) * 32, mb = (wid >> 2) * 64;
    const int m0 = blockIdx.y * BM, n0 = blockIdx.x * BN;

    const int lx7  = l & 7;
    const int arow = (l & 7) + ((l >> 3) & 1) * 8;
    const int agb  = l >> 4;
    const int brow = (l & 7) + ((l >> 4) << 3);
    const int bgb  = (l >> 3) & 1;

    float acc[2][8][4];
#pragma unroll
    for (int i = 0; i < 2; i++)
#pragma unroll
        for (int j = 0; j < 8; j++)
#pragma unroll
            for (int c = 0; c < 4; c++) acc[i][j][c] = 0.0f;

    const int cr = tid >> 3, cc = tid & 7;
    const uint32_t coff = (uint32_t)(cr * 128 + ((cc ^ (cr & 7)) << 4));
    const __half* wsrc = &g_WtOh[(size_t)(n0 + cr) * DIM + cc * 8];
    const __half* xsrc = &g_AOh[(size_t)(m0 + cr) * DIM + cc * 8];

#define O_ISSUE(T) do {                                                     \
        uint32_t sW_ = smb + ((T) & 1) * STAGE_BYTES;                       \
        uint32_t sX_ = sW_ + W_STAGE;                                       \
        _Pragma("unroll")                                                   \
        for (int j = 0; j < 4; j++) {                                       \
            uint32_t o_ = coff + (uint32_t)(j * 32 * 128);                  \
            cp16(sW_ + o_, wsrc + (size_t)(j * 32) * DIM + (T) * BK);       \
            cp16(sX_ + o_, xsrc + (size_t)(j * 32) * DIM + (T) * BK);       \
        }                                                                   \
    } while (0)

    O_ISSUE(0); cp_commit();
    O_ISSUE(1); cp_commit();

#pragma unroll
    for (int kt = 0; kt < NKT; kt++) {
        cp_wait<1>();
        __syncthreads();
        uint32_t sW = smb + (kt & 1) * STAGE_BYTES;
        mma_tile(sW, sW + W_STAGE, nb, mb, lx7, arow, agb, brow, bgb, acc);
        __syncthreads();
        if (kt + 2 < NKT) { O_ISSUE(kt + 2); cp_commit(); }
    }
#undef O_ISSUE

    cp_wait<0>();
    float* Cs = smf;                   // [64 m][132 pitch] fp32
    const int gq = l >> 2, tq = l & 3;
#pragma unroll
    for (int half = 0; half < 2; half++) {
        __syncthreads();
        if ((wid >> 2) == half) {
#pragma unroll
            for (int inf = 0; inf < 2; inf++) {
                int nn = nb + inf * 16 + gq;
#pragma unroll
                for (int jm = 0; jm < 8; jm++) {
                    int mm = jm * 8 + 2 * tq;
                    Cs[mm * 132 + nn]           = acc[inf][jm][0];
                    Cs[(mm + 1) * 132 + nn]     = acc[inf][jm][1];
                    Cs[mm * 132 + nn + 8]       = acc[inf][jm][2];
                    Cs[(mm + 1) * 132 + nn + 8] = acc[inf][jm][3];
                }
            }
        }
        __syncthreads();
#pragma unroll
        for (int it = 0; it < 8; it++) {
            int idx = tid + it * 256;
            int r = idx >> 5, c = (idx & 31) * 4;
            float4 v = *(float4*)&Cs[r * 132 + c];
            v.x += bias[n0 + c];
            v.y += bias[n0 + c + 1];
            v.z += bias[n0 + c + 2];
            v.w += bias[n0 + c + 3];
            *(float4*)&Cext[(size_t)(m0 + half * 64 + r) * ldN + n0 + c] = v;
        }
    }
}

// ---------------- attention: 8 lanes per (b,h), 4 per warp ----------------
__global__ __launch_bounds__(256) void attn_kernel()
{
    const int wid = threadIdx.x >> 5;
    const int lane = threadIdx.x & 31;
    const int grp = lane >> 3;       // 0..3
    const int g   = lane & 7;        // 0..7
    const int bh  = (blockIdx.x * 8 + wid) * 4 + grp;
    const int b = bh >> 3, h = bh & 7;

    const __half* qb  = g_Qh  + (size_t)b * SEQ * DIM       + h * 64 + g * 8;
    const __half* kvb = g_KVh + (size_t)b * SEQ * (2 * DIM) + h * 64 + g * 8;

    uint4 kh[4], vh[4];
    float qf[4][8];
#pragma unroll
    for (int i = 0; i < 4; i++) {
        uint4 qh = *(const uint4*)&qb[i * DIM];
        kh[i] = *(const uint4*)&kvb[i * (2 * DIM)];
        vh[i] = *(const uint4*)&kvb[i * (2 * DIM) + DIM];
        cvt8(qh, qf[i]);
    }

    float s[4][4];
#pragma unroll
    for (int j = 0; j < 4; j++) {
        float kf[8];
        cvt8(kh[j], kf);
#pragma unroll
        for (int i = 0; i < 4; i++) {
            float a = qf[i][0] * kf[0];
#pragma unroll
            for (int d = 1; d < 8; d++) a = fmaf(qf[i][d], kf[d], a);
            s[i][j] = a;
        }
    }
#pragma unroll
    for (int i = 0; i < 4; i++)
#pragma unroll
        for (int j = 0; j < 4; j++)
#pragma unroll
            for (int o = 4; o > 0; o >>= 1)
                s[i][j] += __shfl_xor_sync(0xFFFFFFFFu, s[i][j], o);

    float p[4][4];
#pragma unroll
    for (int i = 0; i < 4; i++) {
        const int jm = 3 - i;                       // masked pair (dist = sqrt2)
#pragma unroll
        for (int j = 0; j < 4; j++) s[i][j] *= SCALE_F;
        s[i][jm] = -(float)(jm + 1) * GAMMA_F;      // finite bias, in denominator

        float mx = fmaxf(fmaxf(s[i][0], s[i][1]), fmaxf(s[i][2], s[i][3]));
        float e0 = __expf(s[i][0] - mx), e1 = __expf(s[i][1] - mx);
        float e2 = __expf(s[i][2] - mx), e3 = __expf(s[i][3] - mx);
        float inv = 1.0f / (e0 + e1 + e2 + e3);
        p[i][0] = e0 * inv; p[i][1] = e1 * inv;
        p[i][2] = e2 * inv; p[i][3] = e3 * inv;
        p[i][jm] = 0.0f;                            // post-softmax mask
    }

    float of[4][8];
#pragma unroll
    for (int i = 0; i < 4; i++)
#pragma unroll
        for (int d = 0; d < 8; d++) of[i][d] = 0.0f;
#pragma unroll
    for (int j = 0; j < 4; j++) {
        float vf[8];
        cvt8(vh[j], vf);
#pragma unroll
        for (int i = 0; i < 4; i++)
#pragma unroll
            for (int d = 0; d < 8; d++)
                of[i][d] = fmaf(p[i][j], vf[d], of[i][d]);
    }

    __half* dst = g_AOh + (size_t)b * SEQ * DIM + h * 64 + g * 8;
#pragma unroll
    for (int i = 0; i < 4; i++) {
        __half2 hh[4];
        hh[0] = __floats2half2_rn(of[i][0], of[i][1]);
        hh[1] = __floats2half2_rn(of[i][2], of[i][3]);
        hh[2] = __floats2half2_rn(of[i][4], of[i][5]);
        hh[3] = __floats2half2_rn(of[i][6], of[i][7]);
        *(uint4*)&dst[i * DIM] = *(uint4*)hh;
    }
}

// ---------------- launch ----------------
extern "C" void kernel_launch(void* const* d_in, const int* in_sizes, int n_in,
                              void* d_out, int out_size)
{
    const float* x   = (const float*)d_in[0];
    const float* ctx = (const float*)d_in[1];
    const float* Wq  = (const float*)d_in[2];
    const float* bq  = (const float*)d_in[3];
    const float* Wkv = (const float*)d_in[4];
    const float* bkv = (const float*)d_in[5];
    const float* Wo  = (const float*)d_in[6];
    const float* bo  = (const float*)d_in[7];
    float* out = (float*)d_out;

    cudaFuncSetAttribute(gemm_qkv, cudaFuncAttributeMaxDynamicSharedMemorySize, SMEM_BYTES);
    cudaFuncSetAttribute(gemm_o, cudaFuncAttributeMaxDynamicSharedMemorySize, SMEM_BYTES);

    // prep: all weights in one launch; both activations in one launch
    transpose_all<<<dim3(16, 64), dim3(32, 8)>>>(Wq, Wkv, Wo);
    to_half2<<<2 * TOH_BLOCKS, 256>>>(x, ctx);

    // Q and KV in one launch (fp16 in/out)
    gemm_qkv<<<dim3(12, ROWS / BM), 256, SMEM_BYTES>>>(bq, bkv);
    // attention: 32 (b,h) per block -> 4096 blocks
    attn_kernel<<<BATCH * HEADS / 32, 256>>>();
    // out = AO @ Wo + bo (fp32 out)
    gemm_o<<<dim3(DIM / BN, ROWS / BM), 256, SMEM_BYTES>>>(bo, out, DIM);
}

// round 14
// speedup vs baseline: 2.0281x; 2.0281x over previous
#include <cuda_runtime.h>
#include <cuda_fp16.h>
#include <cstdint>

// ---------------- problem constants ----------------
#define BATCH   16384
#define SEQ     4
#define DIM     512
#define ROWS    (BATCH * SEQ)      // 65536
#define HEADS   8
#define GAMMA_F 0.4f
#define SCALE_F 0.044194173824159216f  // 512^-0.5

// scratch (allocation-free rule)
__device__ __half g_Qh [ROWS * DIM];          // fp16 Q
__device__ __half g_KVh[ROWS * 2 * DIM];      // fp16 KV
__device__ __half g_AOh[ROWS * DIM];          // fp16 attention output
__device__ __half g_Xh [ROWS * DIM];          // fp16 x
__device__ __half g_Ch [ROWS * DIM];          // fp16 context
// pre-transposed fp16 weights: Wt[n][k]
__device__ __half g_WtQh [DIM * DIM];
__device__ __half g_WtKVh[2 * DIM * DIM];
__device__ __half g_WtOh [DIM * DIM];

// ---------------- GEMM tiling ----------------
#define BM 128
#define BN 128
#define BK 64                       // 64 fp16 = 128B rows
#define NKT (DIM / BK)              // 8
#define STAGES 3
#define W_STAGE 16384
#define X_STAGE 16384
#define STAGE_BYTES (W_STAGE + X_STAGE)
#define SMEM_BYTES (STAGES * STAGE_BYTES)   // 98304 -> 2 CTA/SM

// ---------------- helpers ----------------
__device__ __forceinline__ uint32_t smem_u32(const void* p) {
    uint32_t a;
    asm("{ .reg .u64 t; cvta.to.shared.u64 t, %1; cvt.u32.u64 %0, t; }"
        : "=r"(a) : "l"(p));
    return a;
}
__device__ __forceinline__ void cp16(uint32_t dst, const void* src) {
    asm volatile("cp.async.cg.shared.global [%0], [%1], 16;"
                 :: "r"(dst), "l"(src));
}
__device__ __forceinline__ void cp_commit() {
    asm volatile("cp.async.commit_group;");
}
template <int N>
__device__ __forceinline__ void cp_wait() {
    asm volatile("cp.async.wait_group %0;" :: "n"(N));
}
#define LDSM4(r0, r1, r2, r3, a) \
    asm volatile("ldmatrix.sync.aligned.m8n8.x4.shared.b16 {%0,%1,%2,%3}, [%4];" \
        : "=r"(r0), "=r"(r1), "=r"(r2), "=r"(r3) : "r"(a))

__device__ __forceinline__ void mma_f16(
    float c[4], uint32_t a0, uint32_t a1, uint32_t a2, uint32_t a3,
    uint32_t b0, uint32_t b1)
{
    asm volatile(
        "mma.sync.aligned.m16n8k16.row.col.f32.f16.f16.f32 "
        "{%0,%1,%2,%3}, {%4,%5,%6,%7}, {%8,%9}, {%0,%1,%2,%3};"
        : "+f"(c[0]), "+f"(c[1]), "+f"(c[2]), "+f"(c[3])
        : "r"(a0), "r"(a1), "r"(a2), "r"(a3), "r"(b0), "r"(b1));
}

// unpack 8 halves (uint4) -> 8 floats
__device__ __forceinline__ void cvt8(const uint4& u, float* f) {
    float2 a = __half22float2(*(const __half2*)&u.x);
    float2 b = __half22float2(*(const __half2*)&u.y);
    float2 c = __half22float2(*(const __half2*)&u.z);
    float2 d = __half22float2(*(const __half2*)&u.w);
    f[0] = a.x; f[1] = a.y; f[2] = b.x; f[3] = b.y;
    f[4] = c.x; f[5] = c.y; f[6] = d.x; f[7] = d.y;
}

// ---------------- prep: all 3 weights transposed+rounded in ONE launch ----------------
__global__ void transpose_all(const float* __restrict__ Wq,
                              const float* __restrict__ Wkv,
                              const float* __restrict__ Wo)
{
    int y = blockIdx.y;
    const float* W;
    __half* Wt;
    int N, n0;
    if (y < 16)      { W = Wq;  Wt = g_WtQh;  N = DIM;     n0 = y * 32; }
    else if (y < 48) { W = Wkv; Wt = g_WtKVh; N = 2 * DIM; n0 = (y - 16) * 32; }
    else             { W = Wo;  Wt = g_WtOh;  N = DIM;     n0 = (y - 48) * 32; }

    __shared__ float t[32][33];
    int k0 = blockIdx.x * 32;
    int tx = threadIdx.x, ty = threadIdx.y;
#pragma unroll
    for (int i = ty; i < 32; i += 8)
        t[i][tx] = W[(size_t)(k0 + i) * N + n0 + tx];
    __syncthreads();
#pragma unroll
    for (int i = ty; i < 32; i += 8)
        Wt[(size_t)(n0 + i) * DIM + k0 + tx] = __float2half_rn(t[tx][i]);
}

// ---------------- prep: x AND ctx -> fp16 in ONE launch ----------------
// 8 floats per thread; streaming reads (x/ctx are never read again).
#define TOH_BLOCKS (ROWS * DIM / 8 / 256)     // 16384 per tensor
__global__ void to_half2(const float* __restrict__ x, const float* __restrict__ ctx)
{
    int bid = blockIdx.x;
    const float* src;
    __half* dst;
    int base;
    if (bid < TOH_BLOCKS) { src = x;   dst = g_Xh; base = bid; }
    else                  { src = ctx; dst = g_Ch; base = bid - TOH_BLOCKS; }
    int i = (base * 256 + threadIdx.x) * 8;
    float4 v0 = __ldcs((const float4*)&src[i]);
    float4 v1 = __ldcs((const float4*)&src[i + 4]);
    __half2 h[4];
    h[0] = __floats2half2_rn(v0.x, v0.y);
    h[1] = __floats2half2_rn(v0.z, v0.w);
    h[2] = __floats2half2_rn(v1.x, v1.y);
    h[3] = __floats2half2_rn(v1.z, v1.w);
    *(uint4*)&dst[i] = *(uint4*)h;
}

// shared MMA mainloop body (one k-tile)
__device__ __forceinline__ void mma_tile(
    uint32_t sW, uint32_t sX, int nb, int mb,
    int lx7, int arow, int agb, int brow, int bgb,
    float acc[2][8][4])
{
#pragma unroll
    for (int ks = 0; ks < 4; ks++) {
        uint32_t aw[2][4];
#pragma unroll
        for (int inf = 0; inf < 2; inf++) {
            int row = nb + inf * 16 + arow;
            uint32_t ad = sW + row * 128
                        + (uint32_t)(((2 * ks + agb) ^ lx7) << 4);
            LDSM4(aw[inf][0], aw[inf][1], aw[inf][2], aw[inf][3], ad);
        }
        uint32_t bx[8][2];
#pragma unroll
        for (int jp = 0; jp < 4; jp++) {
            int row = mb + jp * 16 + brow;
            uint32_t ad = sX + row * 128
                        + (uint32_t)(((2 * ks + bgb) ^ lx7) << 4);
            uint32_t r0, r1, r2, r3;
            LDSM4(r0, r1, r2, r3, ad);
            bx[2 * jp][0]     = r0;
            bx[2 * jp][1]     = r1;
            bx[2 * jp + 1][0] = r2;
            bx[2 * jp + 1][1] = r3;
        }
#pragma unroll
        for (int inf = 0; inf < 2; inf++)
#pragma unroll
            for (int jm = 0; jm < 8; jm++)
                mma_f16(acc[inf][jm],
                        aw[inf][0], aw[inf][1], aw[inf][2], aw[inf][3],
                        bx[jm][0], bx[jm][1]);
    }
}

// ---------------- fused Q+KV GEMM (fp16 in, fp16 out) ----------------
// grid.x: 0..3 -> Q n-tiles (Xh @ WtQ), 4..11 -> KV n-tiles (Ch @ WtKV)
__global__ __launch_bounds__(256, 2) void gemm_qkv(
    const float* __restrict__ bq, const float* __restrict__ bkv)
{
    extern __shared__ float smf[];
    const uint32_t smb = smem_u32(smf);

    const int nt = blockIdx.x;
    const int isKV = (nt >= 4);
    const __half* Act  = isKV ? g_Ch : g_Xh;
    const __half* Wt   = isKV ? g_WtKVh : g_WtQh;
    const float* bias  = isKV ? bkv : bq;
    __half* Co         = isKV ? g_KVh : g_Qh;
    const int ldN      = isKV ? 2 * DIM : DIM;
    const int n0       = (isKV ? nt - 4 : nt) * BN;
    const int m0       = blockIdx.y * BM;

    const int tid = threadIdx.x;
    const int wid = tid >> 5;
    const int l   = tid & 31;
    const int nb = (wid & 3) * 32, mb = (wid >> 2) * 64;

    const int lx7  = l & 7;
    const int arow = (l & 7) + ((l >> 3) & 1) * 8;
    const int agb  = l >> 4;
    const int brow = (l & 7) + ((l >> 4) << 3);
    const int bgb  = (l >> 3) & 1;

    float acc[2][8][4];
#pragma unroll
    for (int i = 0; i < 2; i++)
#pragma unroll
        for (int j = 0; j < 8; j++)
#pragma unroll
            for (int c = 0; c < 4; c++) acc[i][j][c] = 0.0f;

    // per-thread copy coords (compile-time invariant)
    const int cr = tid >> 3, cc = tid & 7;
    const uint32_t coff = (uint32_t)(cr * 128 + ((cc ^ (cr & 7)) << 4));
    const __half* wsrc = &Wt[(size_t)(n0 + cr) * DIM + cc * 8];
    const __half* xsrc = &Act[(size_t)(m0 + cr) * DIM + cc * 8];

#define QKV_ISSUE(T) do {                                                   \
        uint32_t sW_ = smb + ((T) % STAGES) * STAGE_BYTES;                  \
        uint32_t sX_ = sW_ + W_STAGE;                                       \
        _Pragma("unroll")                                                   \
        for (int j = 0; j < 4; j++) {                                       \
            uint32_t o_ = coff + (uint32_t)(j * 32 * 128);                  \
            cp16(sW_ + o_, wsrc + (size_t)(j * 32) * DIM + (T) * BK);       \
            cp16(sX_ + o_, xsrc + (size_t)(j * 32) * DIM + (T) * BK);       \
        }                                                                   \
    } while (0)

    QKV_ISSUE(0); cp_commit();
    QKV_ISSUE(1); cp_commit();

#pragma unroll
    for (int kt = 0; kt < NKT; kt++) {
        cp_wait<STAGES - 2>();
        __syncthreads();
        if (kt + STAGES - 1 < NKT) QKV_ISSUE(kt + STAGES - 1);
        cp_commit();
        uint32_t sW = smb + (kt % STAGES) * STAGE_BYTES;
        mma_tile(sW, sW + W_STAGE, nb, mb, lx7, arow, agb, brow, bgb, acc);
    }
#undef QKV_ISSUE

    // epilogue: transpose via smem, bias, fp16 coalesced store
    cp_wait<0>();
    __syncthreads();
    float* Cs = smf;
    const int gq = l >> 2, tq = l & 3;
#pragma unroll
    for (int inf = 0; inf < 2; inf++) {
        int nn = nb + inf * 16 + gq;
#pragma unroll
        for (int jm = 0; jm < 8; jm++) {
            int mm = mb + jm * 8 + 2 * tq;
            Cs[mm * 132 + nn]           = acc[inf][jm][0];
            Cs[(mm + 1) * 132 + nn]     = acc[inf][jm][1];
            Cs[mm * 132 + nn + 8]       = acc[inf][jm][2];
            Cs[(mm + 1) * 132 + nn + 8] = acc[inf][jm][3];
        }
    }
    __syncthreads();
#pragma unroll
    for (int it = 0; it < 8; it++) {
        int idx = tid + it * 256;
        int r = idx >> 4, c = (idx & 15) * 8;
        float4 v0 = *(float4*)&Cs[r * 132 + c];
        float4 v1 = *(float4*)&Cs[r * 132 + c + 4];
        const float* bp = &bias[n0 + c];
        __half2 h[4];
        h[0] = __floats2half2_rn(v0.x + bp[0], v0.y + bp[1]);
        h[1] = __floats2half2_rn(v0.z + bp[2], v0.w + bp[3]);
        h[2] = __floats2half2_rn(v1.x + bp[4], v1.y + bp[5]);
        h[3] = __floats2half2_rn(v1.z + bp[6], v1.w + bp[7]);
        *(uint4*)&Co[(size_t)(m0 + r) * ldN + n0 + c] = *(uint4*)h;
    }
}

// ---------------- O GEMM: fp16 AO in, fp32 out ----------------
__global__ __launch_bounds__(256, 2) void gemm_o(
    const float* __restrict__ bias, float* __restrict__ Cext, int ldN)
{
    extern __shared__ float smf[];
    const uint32_t smb = smem_u32(smf);

    const int tid = threadIdx.x;
    const int wid = tid >> 5;
    const int l   = tid & 31;
    const int nb = (wid & 3) * 32, mb = (wid >> 2) * 64;
    const int m0 = blockIdx.y * BM, n0 = blockIdx.x * BN;

    const int lx7  = l & 7;
    const int arow = (l & 7) + ((l >> 3) & 1) * 8;
    const int agb  = l >> 4;
    const int brow = (l & 7) + ((l >> 4) << 3);
    const int bgb  = (l >> 3) & 1;

    float acc[2][8][4];
#pragma unroll
    for (int i = 0; i < 2; i++)
#pragma unroll
        for (int j = 0; j < 8; j++)
#pragma unroll
            for (int c = 0; c < 4; c++) acc[i][j][c] = 0.0f;

    const int cr = tid >> 3, cc = tid & 7;
    const uint32_t coff = (uint32_t)(cr * 128 + ((cc ^ (cr & 7)) << 4));
    const __half* wsrc = &g_WtOh[(size_t)(n0 + cr) * DIM + cc * 8];
    const __half* xsrc = &g_AOh[(size_t)(m0 + cr) * DIM + cc * 8];

#define O_ISSUE(T) do {                                                     \
        uint32_t sW_ = smb + ((T) % STAGES) * STAGE_BYTES;                  \
        uint32_t sX_ = sW_ + W_STAGE;                                       \
        _Pragma("unroll")                                                   \
        for (int j = 0; j < 4; j++) {                                       \
            uint32_t o_ = coff + (uint32_t)(j * 32 * 128);                  \
            cp16(sW_ + o_, wsrc + (size_t)(j * 32) * DIM + (T) * BK);       \
            cp16(sX_ + o_, xsrc + (size_t)(j * 32) * DIM + (T) * BK);       \
        }                                                                   \
    } while (0)

    O_ISSUE(0); cp_commit();
    O_ISSUE(1); cp_commit();

#pragma unroll
    for (int kt = 0; kt < NKT; kt++) {
        cp_wait<STAGES - 2>();
        __syncthreads();
        if (kt + STAGES - 1 < NKT) O_ISSUE(kt + STAGES - 1);
        cp_commit();
        uint32_t sW = smb + (kt % STAGES) * STAGE_BYTES;
        mma_tile(sW, sW + W_STAGE, nb, mb, lx7, arow, agb, brow, bgb, acc);
    }
#undef O_ISSUE

    cp_wait<0>();
    __syncthreads();
    float* Cs = smf;
    const int gq = l >> 2, tq = l & 3;
#pragma unroll
    for (int inf = 0; inf < 2; inf++) {
        int nn = nb + inf * 16 + gq;
#pragma unroll
        for (int jm = 0; jm < 8; jm++) {
            int mm = mb + jm * 8 + 2 * tq;
            Cs[mm * 132 + nn]           = acc[inf][jm][0];
            Cs[(mm + 1) * 132 + nn]     = acc[inf][jm][1];
            Cs[mm * 132 + nn + 8]       = acc[inf][jm][2];
            Cs[(mm + 1) * 132 + nn + 8] = acc[inf][jm][3];
        }
    }
    __syncthreads();
#pragma unroll
    for (int it = 0; it < 16; it++) {
        int idx = tid + it * 256;
        int r = idx >> 5, c = (idx & 31) * 4;
        float4 v = *(float4*)&Cs[r * 132 + c];
        v.x += bias[n0 + c];
        v.y += bias[n0 + c + 1];
        v.z += bias[n0 + c + 2];
        v.w += bias[n0 + c + 3];
        *(float4*)&Cext[(size_t)(m0 + r) * ldN + n0 + c] = v;
    }
}

// ---------------- attention: 8 lanes per (b,h), 4 per warp ----------------
__global__ __launch_bounds__(256) void attn_kernel()
{
    const int wid = threadIdx.x >> 5;
    const int lane = threadIdx.x & 31;
    const int grp = lane >> 3;       // 0..3
    const int g   = lane & 7;        // 0..7
    const int bh  = (blockIdx.x * 8 + wid) * 4 + grp;
    const int b = bh >> 3, h = bh & 7;

    const __half* qb  = g_Qh  + (size_t)b * SEQ * DIM       + h * 64 + g * 8;
    const __half* kvb = g_KVh + (size_t)b * SEQ * (2 * DIM) + h * 64 + g * 8;

    uint4 kh[4], vh[4];
    float qf[4][8];
#pragma unroll
    for (int i = 0; i < 4; i++) {
        uint4 qh = *(const uint4*)&qb[i * DIM];
        kh[i] = *(const uint4*)&kvb[i * (2 * DIM)];
        vh[i] = *(const uint4*)&kvb[i * (2 * DIM) + DIM];
        cvt8(qh, qf[i]);
    }

    float s[4][4];
#pragma unroll
    for (int j = 0; j < 4; j++) {
        float kf[8];
        cvt8(kh[j], kf);
#pragma unroll
        for (int i = 0; i < 4; i++) {
            float a = qf[i][0] * kf[0];
#pragma unroll
            for (int d = 1; d < 8; d++) a = fmaf(qf[i][d], kf[d], a);
            s[i][j] = a;
        }
    }
#pragma unroll
    for (int i = 0; i < 4; i++)
#pragma unroll
        for (int j = 0; j < 4; j++)
#pragma unroll
            for (int o = 4; o > 0; o >>= 1)
                s[i][j] += __shfl_xor_sync(0xFFFFFFFFu, s[i][j], o);

    float p[4][4];
#pragma unroll
    for (int i = 0; i < 4; i++) {
        const int jm = 3 - i;                       // masked pair (dist = sqrt2)
#pragma unroll
        for (int j = 0; j < 4; j++) s[i][j] *= SCALE_F;
        s[i][jm] = -(float)(jm + 1) * GAMMA_F;      // finite bias, in denominator

        float mx = fmaxf(fmaxf(s[i][0], s[i][1]), fmaxf(s[i][2], s[i][3]));
        float e0 = __expf(s[i][0] - mx), e1 = __expf(s[i][1] - mx);
        float e2 = __expf(s[i][2] - mx), e3 = __expf(s[i][3] - mx);
        float inv = 1.0f / (e0 + e1 + e2 + e3);
        p[i][0] = e0 * inv; p[i][1] = e1 * inv;
        p[i][2] = e2 * inv; p[i][3] = e3 * inv;
        p[i][jm] = 0.0f;                            // post-softmax mask
    }

    float of[4][8];
#pragma unroll
    for (int i = 0; i < 4; i++)
#pragma unroll
        for (int d = 0; d < 8; d++) of[i][d] = 0.0f;
#pragma unroll
    for (int j = 0; j < 4; j++) {
        float vf[8];
        cvt8(vh[j], vf);
#pragma unroll
        for (int i = 0; i < 4; i++)
#pragma unroll
            for (int d = 0; d < 8; d++)
                of[i][d] = fmaf(p[i][j], vf[d], of[i][d]);
    }

    __half* dst = g_AOh + (size_t)b * SEQ * DIM + h * 64 + g * 8;
#pragma unroll
    for (int i = 0; i < 4; i++) {
        __half2 hh[4];
        hh[0] = __floats2half2_rn(of[i][0], of[i][1]);
        hh[1] = __floats2half2_rn(of[i][2], of[i][3]);
        hh[2] = __floats2half2_rn(of[i][4], of[i][5]);
        hh[3] = __floats2half2_rn(of[i][6], of[i][7]);
        *(uint4*)&dst[i * DIM] = *(uint4*)hh;
    }
}

// ---------------- launch ----------------
extern "C" void kernel_launch(void* const* d_in, const int* in_sizes, int n_in,
                              void* d_out, int out_size)
{
    const float* x   = (const float*)d_in[0];
    const float* ctx = (const float*)d_in[1];
    const float* Wq  = (const float*)d_in[2];
    const float* bq  = (const float*)d_in[3];
    const float* Wkv = (const float*)d_in[4];
    const float* bkv = (const float*)d_in[5];
    const float* Wo  = (const float*)d_in[6];
    const float* bo  = (const float*)d_in[7];
    float* out = (float*)d_out;

    cudaFuncSetAttribute(gemm_qkv, cudaFuncAttributeMaxDynamicSharedMemorySize, SMEM_BYTES);
    cudaFuncSetAttribute(gemm_o, cudaFuncAttributeMaxDynamicSharedMemorySize, SMEM_BYTES);

    // prep: all weights in one launch; both activations in one launch
    transpose_all<<<dim3(16, 64), dim3(32, 8)>>>(Wq, Wkv, Wo);
    to_half2<<<2 * TOH_BLOCKS, 256>>>(x, ctx);

    // Q and KV in one launch (fp16 in/out)
    gemm_qkv<<<dim3(12, ROWS / BM), 256, SMEM_BYTES>>>(bq, bkv);
    // attention: 32 (b,h) per block -> 4096 blocks
    attn_kernel<<<BATCH * HEADS / 32, 256>>>();
    // out = AO @ Wo + bo (fp32 out)
    gemm_o<<<dim3(DIM / BN, ROWS / BM), 256, SMEM_BYTES>>>(bo, out, DIM);
}

// round 15
// speedup vs baseline: 2.0515x; 1.0115x over previous
#include <cuda_runtime.h>
#include <cuda_fp16.h>
#include <cstdint>

// ---------------- problem constants ----------------
#define BATCH   16384
#define SEQ     4
#define DIM     512
#define ROWS    (BATCH * SEQ)      // 65536
#define HEADS   8
#define GAMMA_F 0.4f
#define SCALE_F 0.044194173824159216f  // 512^-0.5

// scratch (allocation-free rule)
__device__ __half g_Qh [ROWS * DIM];          // fp16 Q
__device__ __half g_KVh[ROWS * 2 * DIM];      // fp16 KV
__device__ __half g_AOh[ROWS * DIM];          // fp16 attention output
__device__ __half g_Xh [ROWS * DIM];          // fp16 x
__device__ __half g_Ch [ROWS * DIM];          // fp16 context
// pre-transposed fp16 weights: Wt[n][k]
__device__ __half g_WtQh [DIM * DIM];
__device__ __half g_WtKVh[2 * DIM * DIM];
__device__ __half g_WtOh [DIM * DIM];

// ---------------- GEMM tiling ----------------
#define BM 128
#define BN 128
#define BK 64                       // 64 fp16 = 128B rows
#define NKT (DIM / BK)              // 8
#define STAGES 3
#define W_STAGE 16384
#define X_STAGE 16384
#define STAGE_BYTES (W_STAGE + X_STAGE)
#define SMEM_BYTES (STAGES * STAGE_BYTES)   // 98304 -> 2 CTA/SM

// ---------------- helpers ----------------
__device__ __forceinline__ uint32_t smem_u32(const void* p) {
    uint32_t a;
    asm("{ .reg .u64 t; cvta.to.shared.u64 t, %1; cvt.u32.u64 %0, t; }"
        : "=r"(a) : "l"(p));
    return a;
}
__device__ __forceinline__ void cp16(uint32_t dst, const void* src) {
    asm volatile("cp.async.cg.shared.global [%0], [%1], 16;"
                 :: "r"(dst), "l"(src));
}
__device__ __forceinline__ void cp_commit() {
    asm volatile("cp.async.commit_group;");
}
template <int N>
__device__ __forceinline__ void cp_wait() {
    asm volatile("cp.async.wait_group %0;" :: "n"(N));
}
#define LDSM4(r0, r1, r2, r3, a) \
    asm volatile("ldmatrix.sync.aligned.m8n8.x4.shared.b16 {%0,%1,%2,%3}, [%4];" \
        : "=r"(r0), "=r"(r1), "=r"(r2), "=r"(r3) : "r"(a))

__device__ __forceinline__ void mma_f16(
    float c[4], uint32_t a0, uint32_t a1, uint32_t a2, uint32_t a3,
    uint32_t b0, uint32_t b1)
{
    asm volatile(
        "mma.sync.aligned.m16n8k16.row.col.f32.f16.f16.f32 "
        "{%0,%1,%2,%3}, {%4,%5,%6,%7}, {%8,%9}, {%0,%1,%2,%3};"
        : "+f"(c[0]), "+f"(c[1]), "+f"(c[2]), "+f"(c[3])
        : "r"(a0), "r"(a1), "r"(a2), "r"(a3), "r"(b0), "r"(b1));
}

// unpack 8 halves (uint4) -> 8 floats
__device__ __forceinline__ void cvt8(const uint4& u, float* f) {
    float2 a = __half22float2(*(const __half2*)&u.x);
    float2 b = __half22float2(*(const __half2*)&u.y);
    float2 c = __half22float2(*(const __half2*)&u.z);
    float2 d = __half22float2(*(const __half2*)&u.w);
    f[0] = a.x; f[1] = a.y; f[2] = b.x; f[3] = b.y;
    f[4] = c.x; f[5] = c.y; f[6] = d.x; f[7] = d.y;
}

// ---------------- prep (ONE launch): weight transpose + activation convert ----
// blockIdx.x < 1024:  weight transpose blocks (16 k-tiles x 64 n-rows-of-32)
//   y = bid >> 4 selects {Wq: y<16, Wkv: y<48, Wo}, kx = bid & 15
// else: conversion blocks, 8 floats/thread, x then ctx
#define TOH_BLOCKS (ROWS * DIM / 8 / 256)     // 16384 per tensor
#define PREP_TRANSPOSE_BLOCKS 1024            // 16 x 64
__global__ void prep_all(const float* __restrict__ Wq,
                         const float* __restrict__ Wkv,
                         const float* __restrict__ Wo,
                         const float* __restrict__ x,
                         const float* __restrict__ ctx)
{
    int bid = blockIdx.x;
    if (bid < PREP_TRANSPOSE_BLOCKS) {
        int kx = bid & 15;
        int y  = bid >> 4;
        const float* W;
        __half* Wt;
        int N, n0;
        if (y < 16)      { W = Wq;  Wt = g_WtQh;  N = DIM;     n0 = y * 32; }
        else if (y < 48) { W = Wkv; Wt = g_WtKVh; N = 2 * DIM; n0 = (y - 16) * 32; }
        else             { W = Wo;  Wt = g_WtOh;  N = DIM;     n0 = (y - 48) * 32; }

        __shared__ float t[32][33];
        int k0 = kx * 32;
        int tx = threadIdx.x & 31, ty = threadIdx.x >> 5;
#pragma unroll
        for (int i = ty; i < 32; i += 8)
            t[i][tx] = W[(size_t)(k0 + i) * N + n0 + tx];
        __syncthreads();
#pragma unroll
        for (int i = ty; i < 32; i += 8)
            Wt[(size_t)(n0 + i) * DIM + k0 + tx] = __float2half_rn(t[tx][i]);
    } else {
        int cb = bid - PREP_TRANSPOSE_BLOCKS;
        const float* src;
        __half* dst;
        int base;
        if (cb < TOH_BLOCKS) { src = x;   dst = g_Xh; base = cb; }
        else                 { src = ctx; dst = g_Ch; base = cb - TOH_BLOCKS; }
        int i = (base * 256 + threadIdx.x) * 8;
        float4 v0 = __ldcs((const float4*)&src[i]);
        float4 v1 = __ldcs((const float4*)&src[i + 4]);
        __half2 h[4];
        h[0] = __floats2half2_rn(v0.x, v0.y);
        h[1] = __floats2half2_rn(v0.z, v0.w);
        h[2] = __floats2half2_rn(v1.x, v1.y);
        h[3] = __floats2half2_rn(v1.z, v1.w);
        *(uint4*)&dst[i] = *(uint4*)h;
    }
}

// shared MMA mainloop body (one k-tile)
__device__ __forceinline__ void mma_tile(
    uint32_t sW, uint32_t sX, int nb, int mb,
    int lx7, int arow, int agb, int brow, int bgb,
    float acc[2][8][4])
{
#pragma unroll
    for (int ks = 0; ks < 4; ks++) {
        uint32_t aw[2][4];
#pragma unroll
        for (int inf = 0; inf < 2; inf++) {
            int row = nb + inf * 16 + arow;
            uint32_t ad = sW + row * 128
                        + (uint32_t)(((2 * ks + agb) ^ lx7) << 4);
            LDSM4(aw[inf][0], aw[inf][1], aw[inf][2], aw[inf][3], ad);
        }
        uint32_t bx[8][2];
#pragma unroll
        for (int jp = 0; jp < 4; jp++) {
            int row = mb + jp * 16 + brow;
            uint32_t ad = sX + row * 128
                        + (uint32_t)(((2 * ks + bgb) ^ lx7) << 4);
            uint32_t r0, r1, r2, r3;
            LDSM4(r0, r1, r2, r3, ad);
            bx[2 * jp][0]     = r0;
            bx[2 * jp][1]     = r1;
            bx[2 * jp + 1][0] = r2;
            bx[2 * jp + 1][1] = r3;
        }
#pragma unroll
        for (int inf = 0; inf < 2; inf++)
#pragma unroll
            for (int jm = 0; jm < 8; jm++)
                mma_f16(acc[inf][jm],
                        aw[inf][0], aw[inf][1], aw[inf][2], aw[inf][3],
                        bx[jm][0], bx[jm][1]);
    }
}

// ---------------- fused Q+KV GEMM (fp16 in, fp16 out) ----------------
// grid.x: 0..3 -> Q n-tiles (Xh @ WtQ), 4..11 -> KV n-tiles (Ch @ WtKV)
__global__ __launch_bounds__(256, 2) void gemm_qkv(
    const float* __restrict__ bq, const float* __restrict__ bkv)
{
    extern __shared__ float smf[];
    const uint32_t smb = smem_u32(smf);

    const int nt = blockIdx.x;
    const int isKV = (nt >= 4);
    const __half* Act  = isKV ? g_Ch : g_Xh;
    const __half* Wt   = isKV ? g_WtKVh : g_WtQh;
    const float* bias  = isKV ? bkv : bq;
    __half* Co         = isKV ? g_KVh : g_Qh;
    const int ldN      = isKV ? 2 * DIM : DIM;
    const int n0       = (isKV ? nt - 4 : nt) * BN;
    const int m0       = blockIdx.y * BM;

    const int tid = threadIdx.x;
    const int wid = tid >> 5;
    const int l   = tid & 31;
    const int nb = (wid & 3) * 32, mb = (wid >> 2) * 64;

    const int lx7  = l & 7;
    const int arow = (l & 7) + ((l >> 3) & 1) * 8;
    const int agb  = l >> 4;
    const int brow = (l & 7) + ((l >> 4) << 3);
    const int bgb  = (l >> 3) & 1;

    float acc[2][8][4];
#pragma unroll
    for (int i = 0; i < 2; i++)
#pragma unroll
        for (int j = 0; j < 8; j++)
#pragma unroll
            for (int c = 0; c < 4; c++) acc[i][j][c] = 0.0f;

    const int cr = tid >> 3, cc = tid & 7;
    const uint32_t coff = (uint32_t)(cr * 128 + ((cc ^ (cr & 7)) << 4));
    const __half* wsrc = &Wt[(size_t)(n0 + cr) * DIM + cc * 8];
    const __half* xsrc = &Act[(size_t)(m0 + cr) * DIM + cc * 8];

#define QKV_ISSUE(T) do {                                                   \
        uint32_t sW_ = smb + ((T) % STAGES) * STAGE_BYTES;                  \
        uint32_t sX_ = sW_ + W_STAGE;                                       \
        _Pragma("unroll")                                                   \
        for (int j = 0; j < 4; j++) {                                       \
            uint32_t o_ = coff + (uint32_t)(j * 32 * 128);                  \
            cp16(sW_ + o_, wsrc + (size_t)(j * 32) * DIM + (T) * BK);       \
            cp16(sX_ + o_, xsrc + (size_t)(j * 32) * DIM + (T) * BK);       \
        }                                                                   \
    } while (0)

    QKV_ISSUE(0); cp_commit();
    QKV_ISSUE(1); cp_commit();

#pragma unroll
    for (int kt = 0; kt < NKT; kt++) {
        cp_wait<STAGES - 2>();
        __syncthreads();
        if (kt + STAGES - 1 < NKT) QKV_ISSUE(kt + STAGES - 1);
        cp_commit();
        uint32_t sW = smb + (kt % STAGES) * STAGE_BYTES;
        mma_tile(sW, sW + W_STAGE, nb, mb, lx7, arow, agb, brow, bgb, acc);
    }
#undef QKV_ISSUE

    // epilogue: transpose via smem, bias, fp16 coalesced store
    cp_wait<0>();
    __syncthreads();
    float* Cs = smf;
    const int gq = l >> 2, tq = l & 3;
#pragma unroll
    for (int inf = 0; inf < 2; inf++) {
        int nn = nb + inf * 16 + gq;
#pragma unroll
        for (int jm = 0; jm < 8; jm++) {
            int mm = mb + jm * 8 + 2 * tq;
            Cs[mm * 132 + nn]           = acc[inf][jm][0];
            Cs[(mm + 1) * 132 + nn]     = acc[inf][jm][1];
            Cs[mm * 132 + nn + 8]       = acc[inf][jm][2];
            Cs[(mm + 1) * 132 + nn + 8] = acc[inf][jm][3];
        }
    }
    __syncthreads();
#pragma unroll
    for (int it = 0; it < 8; it++) {
        int idx = tid + it * 256;
        int r = idx >> 4, c = (idx & 15) * 8;
        float4 v0 = *(float4*)&Cs[r * 132 + c];
        float4 v1 = *(float4*)&Cs[r * 132 + c + 4];
        const float* bp = &bias[n0 + c];
        __half2 h[4];
        h[0] = __floats2half2_rn(v0.x + bp[0], v0.y + bp[1]);
        h[1] = __floats2half2_rn(v0.z + bp[2], v0.w + bp[3]);
        h[2] = __floats2half2_rn(v1.x + bp[4], v1.y + bp[5]);
        h[3] = __floats2half2_rn(v1.z + bp[6], v1.w + bp[7]);
        *(uint4*)&Co[(size_t)(m0 + r) * ldN + n0 + c] = *(uint4*)h;
    }
}

// ---------------- O GEMM: fp16 AO in, fp32 out ----------------
__global__ __launch_bounds__(256, 2) void gemm_o(
    const float* __restrict__ bias, float* __restrict__ Cext, int ldN)
{
    extern __shared__ float smf[];
    const uint32_t smb = smem_u32(smf);

    const int tid = threadIdx.x;
    const int wid = tid >> 5;
    const int l   = tid & 31;
    const int nb = (wid & 3) * 32, mb = (wid >> 2) * 64;
    const int m0 = blockIdx.y * BM, n0 = blockIdx.x * BN;

    const int lx7  = l & 7;
    const int arow = (l & 7) + ((l >> 3) & 1) * 8;
    const int agb  = l >> 4;
    const int brow = (l & 7) + ((l >> 4) << 3);
    const int bgb  = (l >> 3) & 1;

    float acc[2][8][4];
#pragma unroll
    for (int i = 0; i < 2; i++)
#pragma unroll
        for (int j = 0; j < 8; j++)
#pragma unroll
            for (int c = 0; c < 4; c++) acc[i][j][c] = 0.0f;

    const int cr = tid >> 3, cc = tid & 7;
    const uint32_t coff = (uint32_t)(cr * 128 + ((cc ^ (cr & 7)) << 4));
    const __half* wsrc = &g_WtOh[(size_t)(n0 + cr) * DIM + cc * 8];
    const __half* xsrc = &g_AOh[(size_t)(m0 + cr) * DIM + cc * 8];

#define O_ISSUE(T) do {                                                     \
        uint32_t sW_ = smb + ((T) % STAGES) * STAGE_BYTES;                  \
        uint32_t sX_ = sW_ + W_STAGE;                                       \
        _Pragma("unroll")                                                   \
        for (int j = 0; j < 4; j++) {                                       \
            uint32_t o_ = coff + (uint32_t)(j * 32 * 128);                  \
            cp16(sW_ + o_, wsrc + (size_t)(j * 32) * DIM + (T) * BK);       \
            cp16(sX_ + o_, xsrc + (size_t)(j * 32) * DIM + (T) * BK);       \
        }                                                                   \
    } while (0)

    O_ISSUE(0); cp_commit();
    O_ISSUE(1); cp_commit();

#pragma unroll
    for (int kt = 0; kt < NKT; kt++) {
        cp_wait<STAGES - 2>();
        __syncthreads();
        if (kt + STAGES - 1 < NKT) O_ISSUE(kt + STAGES - 1);
        cp_commit();
        uint32_t sW = smb + (kt % STAGES) * STAGE_BYTES;
        mma_tile(sW, sW + W_STAGE, nb, mb, lx7, arow, agb, brow, bgb, acc);
    }
#undef O_ISSUE

    cp_wait<0>();
    __syncthreads();
    float* Cs = smf;
    const int gq = l >> 2, tq = l & 3;
#pragma unroll
    for (int inf = 0; inf < 2; inf++) {
        int nn = nb + inf * 16 + gq;
#pragma unroll
        for (int jm = 0; jm < 8; jm++) {
            int mm = mb + jm * 8 + 2 * tq;
            Cs[mm * 132 + nn]           = acc[inf][jm][0];
            Cs[(mm + 1) * 132 + nn]     = acc[inf][jm][1];
            Cs[mm * 132 + nn + 8]       = acc[inf][jm][2];
            Cs[(mm + 1) * 132 + nn + 8] = acc[inf][jm][3];
        }
    }
    __syncthreads();
#pragma unroll
    for (int it = 0; it < 16; it++) {
        int idx = tid + it * 256;
        int r = idx >> 5, c = (idx & 31) * 4;
        float4 v = *(float4*)&Cs[r * 132 + c];
        v.x += bias[n0 + c];
        v.y += bias[n0 + c + 1];
        v.z += bias[n0 + c + 2];
        v.w += bias[n0 + c + 3];
        *(float4*)&Cext[(size_t)(m0 + r) * ldN + n0 + c] = v;
    }
}

// ---------------- attention: 8 lanes per (b,h), 4 per warp ----------------
__global__ __launch_bounds__(256) void attn_kernel()
{
    const int wid = threadIdx.x >> 5;
    const int lane = threadIdx.x & 31;
    const int grp = lane >> 3;       // 0..3
    const int g   = lane & 7;        // 0..7
    const int bh  = (blockIdx.x * 8 + wid) * 4 + grp;
    const int b = bh >> 3, h = bh & 7;

    const __half* qb  = g_Qh  + (size_t)b * SEQ * DIM       + h * 64 + g * 8;
    const __half* kvb = g_KVh + (size_t)b * SEQ * (2 * DIM) + h * 64 + g * 8;

    uint4 kh[4], vh[4];
    float qf[4][8];
#pragma unroll
    for (int i = 0; i < 4; i++) {
        uint4 qh = *(const uint4*)&qb[i * DIM];
        kh[i] = *(const uint4*)&kvb[i * (2 * DIM)];
        vh[i] = *(const uint4*)&kvb[i * (2 * DIM) + DIM];
        cvt8(qh, qf[i]);
    }

    float s[4][4];
#pragma unroll
    for (int j = 0; j < 4; j++) {
        float kf[8];
        cvt8(kh[j], kf);
#pragma unroll
        for (int i = 0; i < 4; i++) {
            float a = qf[i][0] * kf[0];
#pragma unroll
            for (int d = 1; d < 8; d++) a = fmaf(qf[i][d], kf[d], a);
            s[i][j] = a;
        }
    }
#pragma unroll
    for (int i = 0; i < 4; i++)
#pragma unroll
        for (int j = 0; j < 4; j++)
#pragma unroll
            for (int o = 4; o > 0; o >>= 1)
                s[i][j] += __shfl_xor_sync(0xFFFFFFFFu, s[i][j], o);

    float p[4][4];
#pragma unroll
    for (int i = 0; i < 4; i++) {
        const int jm = 3 - i;                       // masked pair (dist = sqrt2)
#pragma unroll
        for (int j = 0; j < 4; j++) s[i][j] *= SCALE_F;
        s[i][jm] = -(float)(jm + 1) * GAMMA_F;      // finite bias, in denominator

        float mx = fmaxf(fmaxf(s[i][0], s[i][1]), fmaxf(s[i][2], s[i][3]));
        float e0 = __expf(s[i][0] - mx), e1 = __expf(s[i][1] - mx);
        float e2 = __expf(s[i][2] - mx), e3 = __expf(s[i][3] - mx);
        float inv = 1.0f / (e0 + e1 + e2 + e3);
        p[i][0] = e0 * inv; p[i][1] = e1 * inv;
        p[i][2] = e2 * inv; p[i][3] = e3 * inv;
        p[i][jm] = 0.0f;                            // post-softmax mask
    }

    float of[4][8];
#pragma unroll
    for (int i = 0; i < 4; i++)
#pragma unroll
        for (int d = 0; d < 8; d++) of[i][d] = 0.0f;
#pragma unroll
    for (int j = 0; j < 4; j++) {
        float vf[8];
        cvt8(vh[j], vf);
#pragma unroll
        for (int i = 0; i < 4; i++)
#pragma unroll
            for (int d = 0; d < 8; d++)
                of[i][d] = fmaf(p[i][j], vf[d], of[i][d]);
    }

    __half* dst = g_AOh + (size_t)b * SEQ * DIM + h * 64 + g * 8;
#pragma unroll
    for (int i = 0; i < 4; i++) {
        __half2 hh[4];
        hh[0] = __floats2half2_rn(of[i][0], of[i][1]);
        hh[1] = __floats2half2_rn(of[i][2], of[i][3]);
        hh[2] = __floats2half2_rn(of[i][4], of[i][5]);
        hh[3] = __floats2half2_rn(of[i][6], of[i][7]);
        *(uint4*)&dst[i * DIM] = *(uint4*)hh;
    }
}

// ---------------- launch ----------------
extern "C" void kernel_launch(void* const* d_in, const int* in_sizes, int n_in,
                              void* d_out, int out_size)
{
    const float* x   = (const float*)d_in[0];
    const float* ctx = (const float*)d_in[1];
    const float* Wq  = (const float*)d_in[2];
    const float* bq  = (const float*)d_in[3];
    const float* Wkv = (const float*)d_in[4];
    const float* bkv = (const float*)d_in[5];
    const float* Wo  = (const float*)d_in[6];
    const float* bo  = (const float*)d_in[7];
    float* out = (float*)d_out;

    cudaFuncSetAttribute(gemm_qkv, cudaFuncAttributeMaxDynamicSharedMemorySize, SMEM_BYTES);
    cudaFuncSetAttribute(gemm_o, cudaFuncAttributeMaxDynamicSharedMemorySize, SMEM_BYTES);

    // prep: weight transpose + both activation conversions in ONE launch
    prep_all<<<PREP_TRANSPOSE_BLOCKS + 2 * TOH_BLOCKS, 256>>>(Wq, Wkv, Wo, x, ctx);

    // Q and KV in one launch (fp16 in/out)
    gemm_qkv<<<dim3(12, ROWS / BM), 256, SMEM_BYTES>>>(bq, bkv);
    // attention: 32 (b,h) per block -> 4096 blocks
    attn_kernel<<<BATCH * HEADS / 32, 256>>>();
    // out = AO @ Wo + bo (fp32 out)
    gemm_o<<<dim3(DIM / BN, ROWS / BM), 256, SMEM_BYTES>>>(bo, out, DIM);
}

// round 16
// speedup vs baseline: 2.0650x; 1.0066x over previous
#include <cuda_runtime.h>
#include <cuda_fp16.h>
#include <cstdint>

// ---------------- problem constants ----------------
#define BATCH   16384
#define SEQ     4
#define DIM     512
#define ROWS    (BATCH * SEQ)      // 65536
#define HEADS   8
#define GAMMA_F 0.4f
#define SCALE_F 0.044194173824159216f  // 512^-0.5

// scratch (allocation-free rule)
__device__ __half g_Qh [ROWS * DIM];          // fp16 Q
__device__ __half g_KVh[ROWS * 2 * DIM];      // fp16 KV
__device__ __half g_AOh[ROWS * DIM];          // fp16 attention output
__device__ __half g_Xh [ROWS * DIM];          // fp16 x
__device__ __half g_Ch [ROWS * DIM];          // fp16 context
// pre-transposed fp16 weights: Wt[n][k]
__device__ __half g_WtQh [DIM * DIM];
__device__ __half g_WtKVh[2 * DIM * DIM];
__device__ __half g_WtOh [DIM * DIM];

// ---------------- GEMM tiling ----------------
#define BM 128
#define BN 128
#define BK 64                       // 64 fp16 = 128B rows
#define NKT (DIM / BK)              // 8
#define STAGES 3
#define W_STAGE 16384
#define X_STAGE 16384
#define STAGE_BYTES (W_STAGE + X_STAGE)
#define SMEM_BYTES (STAGES * STAGE_BYTES)   // 98304 -> 2 CTA/SM

// ---------------- helpers ----------------
__device__ __forceinline__ uint32_t smem_u32(const void* p) {
    uint32_t a;
    asm("{ .reg .u64 t; cvta.to.shared.u64 t, %1; cvt.u32.u64 %0, t; }"
        : "=r"(a) : "l"(p));
    return a;
}
__device__ __forceinline__ void cp16(uint32_t dst, const void* src) {
    asm volatile("cp.async.cg.shared.global [%0], [%1], 16;"
                 :: "r"(dst), "l"(src));
}
__device__ __forceinline__ void cp_commit() {
    asm volatile("cp.async.commit_group;");
}
template <int N>
__device__ __forceinline__ void cp_wait() {
    asm volatile("cp.async.wait_group %0;" :: "n"(N));
}
#define LDSM4(r0, r1, r2, r3, a) \
    asm volatile("ldmatrix.sync.aligned.m8n8.x4.shared.b16 {%0,%1,%2,%3}, [%4];" \
        : "=r"(r0), "=r"(r1), "=r"(r2), "=r"(r3) : "r"(a))

__device__ __forceinline__ void mma_f16(
    float c[4], uint32_t a0, uint32_t a1, uint32_t a2, uint32_t a3,
    uint32_t b0, uint32_t b1)
{
    asm volatile(
        "mma.sync.aligned.m16n8k16.row.col.f32.f16.f16.f32 "
        "{%0,%1,%2,%3}, {%4,%5,%6,%7}, {%8,%9}, {%0,%1,%2,%3};"
        : "+f"(c[0]), "+f"(c[1]), "+f"(c[2]), "+f"(c[3])
        : "r"(a0), "r"(a1), "r"(a2), "r"(a3), "r"(b0), "r"(b1));
}

// unpack 8 halves (uint4) -> 8 floats
__device__ __forceinline__ void cvt8(const uint4& u, float* f) {
    float2 a = __half22float2(*(const __half2*)&u.x);
    float2 b = __half22float2(*(const __half2*)&u.y);
    float2 c = __half22float2(*(const __half2*)&u.z);
    float2 d = __half22float2(*(const __half2*)&u.w);
    f[0] = a.x; f[1] = a.y; f[2] = b.x; f[3] = b.y;
    f[4] = c.x; f[5] = c.y; f[6] = d.x; f[7] = d.y;
}

// ---------------- prep (ONE launch): weight transpose + activation convert ----
// blockIdx.x < 1024: weight transpose (16 k-tiles x 64 n-rows-of-32)
// else: conversion blocks, 16 floats/thread (4x LDG.128 streaming), x then ctx
#define TOH_BLOCKS (ROWS * DIM / 16 / 256)    // 8192 per tensor
#define PREP_TRANSPOSE_BLOCKS 1024            // 16 x 64
__global__ void prep_all(const float* __restrict__ Wq,
                         const float* __restrict__ Wkv,
                         const float* __restrict__ Wo,
                         const float* __restrict__ x,
                         const float* __restrict__ ctx)
{
    int bid = blockIdx.x;
    if (bid < PREP_TRANSPOSE_BLOCKS) {
        int kx = bid & 15;
        int y  = bid >> 4;
        const float* W;
        __half* Wt;
        int N, n0;
        if (y < 16)      { W = Wq;  Wt = g_WtQh;  N = DIM;     n0 = y * 32; }
        else if (y < 48) { W = Wkv; Wt = g_WtKVh; N = 2 * DIM; n0 = (y - 16) * 32; }
        else             { W = Wo;  Wt = g_WtOh;  N = DIM;     n0 = (y - 48) * 32; }

        __shared__ float t[32][33];
        int k0 = kx * 32;
        int tx = threadIdx.x & 31, ty = threadIdx.x >> 5;
#pragma unroll
        for (int i = ty; i < 32; i += 8)
            t[i][tx] = W[(size_t)(k0 + i) * N + n0 + tx];
        __syncthreads();
#pragma unroll
        for (int i = ty; i < 32; i += 8)
            Wt[(size_t)(n0 + i) * DIM + k0 + tx] = __float2half_rn(t[tx][i]);
    } else {
        int cb = bid - PREP_TRANSPOSE_BLOCKS;
        const float* src;
        __half* dst;
        int base;
        if (cb < TOH_BLOCKS) { src = x;   dst = g_Xh; base = cb; }
        else                 { src = ctx; dst = g_Ch; base = cb - TOH_BLOCKS; }
        int i = (base * 256 + threadIdx.x) * 16;
        float4 v0 = __ldcs((const float4*)&src[i]);
        float4 v1 = __ldcs((const float4*)&src[i + 4]);
        float4 v2 = __ldcs((const float4*)&src[i + 8]);
        float4 v3 = __ldcs((const float4*)&src[i + 12]);
        __half2 h[8];
        h[0] = __floats2half2_rn(v0.x, v0.y);
        h[1] = __floats2half2_rn(v0.z, v0.w);
        h[2] = __floats2half2_rn(v1.x, v1.y);
        h[3] = __floats2half2_rn(v1.z, v1.w);
        h[4] = __floats2half2_rn(v2.x, v2.y);
        h[5] = __floats2half2_rn(v2.z, v2.w);
        h[6] = __floats2half2_rn(v3.x, v3.y);
        h[7] = __floats2half2_rn(v3.z, v3.w);
        *(uint4*)&dst[i]     = *(uint4*)&h[0];
        *(uint4*)&dst[i + 8] = *(uint4*)&h[4];
    }
}

// shared MMA mainloop body (one k-tile)
__device__ __forceinline__ void mma_tile(
    uint32_t sW, uint32_t sX, int nb, int mb,
    int lx7, int arow, int agb, int brow, int bgb,
    float acc[2][8][4])
{
#pragma unroll
    for (int ks = 0; ks < 4; ks++) {
        uint32_t aw[2][4];
#pragma unroll
        for (int inf = 0; inf < 2; inf++) {
            int row = nb + inf * 16 + arow;
            uint32_t ad = sW + row * 128
                        + (uint32_t)(((2 * ks + agb) ^ lx7) << 4);
            LDSM4(aw[inf][0], aw[inf][1], aw[inf][2], aw[inf][3], ad);
        }
        uint32_t bx[8][2];
#pragma unroll
        for (int jp = 0; jp < 4; jp++) {
            int row = mb + jp * 16 + brow;
            uint32_t ad = sX + row * 128
                        + (uint32_t)(((2 * ks + bgb) ^ lx7) << 4);
            uint32_t r0, r1, r2, r3;
            LDSM4(r0, r1, r2, r3, ad);
            bx[2 * jp][0]     = r0;
            bx[2 * jp][1]     = r1;
            bx[2 * jp + 1][0] = r2;
            bx[2 * jp + 1][1] = r3;
        }
#pragma unroll
        for (int inf = 0; inf < 2; inf++)
#pragma unroll
            for (int jm = 0; jm < 8; jm++)
                mma_f16(acc[inf][jm],
                        aw[inf][0], aw[inf][1], aw[inf][2], aw[inf][3],
                        bx[jm][0], bx[jm][1]);
    }
}

// ---------------- fused Q+KV GEMM (fp16 in, fp16 out) ----------------
// grid.x: 0..3 -> Q n-tiles (Xh @ WtQ), 4..11 -> KV n-tiles (Ch @ WtKV)
__global__ __launch_bounds__(256, 2) void gemm_qkv(
    const float* __restrict__ bq, const float* __restrict__ bkv)
{
    extern __shared__ float smf[];
    const uint32_t smb = smem_u32(smf);

    const int nt = blockIdx.x;
    const int isKV = (nt >= 4);
    const __half* Act  = isKV ? g_Ch : g_Xh;
    const __half* Wt   = isKV ? g_WtKVh : g_WtQh;
    const float* bias  = isKV ? bkv : bq;
    __half* Co         = isKV ? g_KVh : g_Qh;
    const int ldN      = isKV ? 2 * DIM : DIM;
    const int n0       = (isKV ? nt - 4 : nt) * BN;
    const int m0       = blockIdx.y * BM;

    const int tid = threadIdx.x;
    const int wid = tid >> 5;
    const int l   = tid & 31;
    const int nb = (wid & 3) * 32, mb = (wid >> 2) * 64;

    const int lx7  = l & 7;
    const int arow = (l & 7) + ((l >> 3) & 1) * 8;
    const int agb  = l >> 4;
    const int brow = (l & 7) + ((l >> 4) << 3);
    const int bgb  = (l >> 3) & 1;

    float acc[2][8][4];
#pragma unroll
    for (int i = 0; i < 2; i++)
#pragma unroll
        for (int j = 0; j < 8; j++)
#pragma unroll
            for (int c = 0; c < 4; c++) acc[i][j][c] = 0.0f;

    const int cr = tid >> 3, cc = tid & 7;
    const uint32_t coff = (uint32_t)(cr * 128 + ((cc ^ (cr & 7)) << 4));
    const __half* wsrc = &Wt[(size_t)(n0 + cr) * DIM + cc * 8];
    const __half* xsrc = &Act[(size_t)(m0 + cr) * DIM + cc * 8];

#define QKV_ISSUE(T) do {                                                   \
        uint32_t sW_ = smb + ((T) % STAGES) * STAGE_BYTES;                  \
        uint32_t sX_ = sW_ + W_STAGE;                                       \
        _Pragma("unroll")                                                   \
        for (int j = 0; j < 4; j++) {                                       \
            uint32_t o_ = coff + (uint32_t)(j * 32 * 128);                  \
            cp16(sW_ + o_, wsrc + (size_t)(j * 32) * DIM + (T) * BK);       \
            cp16(sX_ + o_, xsrc + (size_t)(j * 32) * DIM + (T) * BK);       \
        }                                                                   \
    } while (0)

    QKV_ISSUE(0); cp_commit();
    QKV_ISSUE(1); cp_commit();

#pragma unroll
    for (int kt = 0; kt < NKT; kt++) {
        cp_wait<STAGES - 2>();
        __syncthreads();
        if (kt + STAGES - 1 < NKT) QKV_ISSUE(kt + STAGES - 1);
        cp_commit();
        uint32_t sW = smb + (kt % STAGES) * STAGE_BYTES;
        mma_tile(sW, sW + W_STAGE, nb, mb, lx7, arow, agb, brow, bgb, acc);
    }
#undef QKV_ISSUE

    // epilogue: transpose via smem, bias, fp16 coalesced store
    cp_wait<0>();
    __syncthreads();
    float* Cs = smf;
    const int gq = l >> 2, tq = l & 3;
#pragma unroll
    for (int inf = 0; inf < 2; inf++) {
        int nn = nb + inf * 16 + gq;
#pragma unroll
        for (int jm = 0; jm < 8; jm++) {
            int mm = mb + jm * 8 + 2 * tq;
            Cs[mm * 132 + nn]           = acc[inf][jm][0];
            Cs[(mm + 1) * 132 + nn]     = acc[inf][jm][1];
            Cs[mm * 132 + nn + 8]       = acc[inf][jm][2];
            Cs[(mm + 1) * 132 + nn + 8] = acc[inf][jm][3];
        }
    }
    __syncthreads();
#pragma unroll
    for (int it = 0; it < 8; it++) {
        int idx = tid + it * 256;
        int r = idx >> 4, c = (idx & 15) * 8;
        float4 v0 = *(float4*)&Cs[r * 132 + c];
        float4 v1 = *(float4*)&Cs[r * 132 + c + 4];
        const float* bp = &bias[n0 + c];
        __half2 h[4];
        h[0] = __floats2half2_rn(v0.x + bp[0], v0.y + bp[1]);
        h[1] = __floats2half2_rn(v0.z + bp[2], v0.w + bp[3]);
        h[2] = __floats2half2_rn(v1.x + bp[4], v1.y + bp[5]);
        h[3] = __floats2half2_rn(v1.z + bp[6], v1.w + bp[7]);
        *(uint4*)&Co[(size_t)(m0 + r) * ldN + n0 + c] = *(uint4*)h;
    }
}

// ---------------- O GEMM: fp16 AO in, fp32 out ----------------
__global__ __launch_bounds__(256, 2) void gemm_o(
    const float* __restrict__ bias, float* __restrict__ Cext, int ldN)
{
    extern __shared__ float smf[];
    const uint32_t smb = smem_u32(smf);

    const int tid = threadIdx.x;
    const int wid = tid >> 5;
    const int l   = tid & 31;
    const int nb = (wid & 3) * 32, mb = (wid >> 2) * 64;
    const int m0 = blockIdx.y * BM, n0 = blockIdx.x * BN;

    const int lx7  = l & 7;
    const int arow = (l & 7) + ((l >> 3) & 1) * 8;
    const int agb  = l >> 4;
    const int brow = (l & 7) + ((l >> 4) << 3);
    const int bgb  = (l >> 3) & 1;

    float acc[2][8][4];
#pragma unroll
    for (int i = 0; i < 2; i++)
#pragma unroll
        for (int j = 0; j < 8; j++)
#pragma unroll
            for (int c = 0; c < 4; c++) acc[i][j][c] = 0.0f;

    const int cr = tid >> 3, cc = tid & 7;
    const uint32_t coff = (uint32_t)(cr * 128 + ((cc ^ (cr & 7)) << 4));
    const __half* wsrc = &g_WtOh[(size_t)(n0 + cr) * DIM + cc * 8];
    const __half* xsrc = &g_AOh[(size_t)(m0 + cr) * DIM + cc * 8];

#define O_ISSUE(T) do {                                                     \
        uint32_t sW_ = smb + ((T) % STAGES) * STAGE_BYTES;                  \
        uint32_t sX_ = sW_ + W_STAGE;                                       \
        _Pragma("unroll")                                                   \
        for (int j = 0; j < 4; j++) {                                       \
            uint32_t o_ = coff + (uint32_t)(j * 32 * 128);                  \
            cp16(sW_ + o_, wsrc + (size_t)(j * 32) * DIM + (T) * BK);       \
            cp16(sX_ + o_, xsrc + (size_t)(j * 32) * DIM + (T) * BK);       \
        }                                                                   \
    } while (0)

    O_ISSUE(0); cp_commit();
    O_ISSUE(1); cp_commit();

#pragma unroll
    for (int kt = 0; kt < NKT; kt++) {
        cp_wait<STAGES - 2>();
        __syncthreads();
        if (kt + STAGES - 1 < NKT) O_ISSUE(kt + STAGES - 1);
        cp_commit();
        uint32_t sW = smb + (kt % STAGES) * STAGE_BYTES;
        mma_tile(sW, sW + W_STAGE, nb, mb, lx7, arow, agb, brow, bgb, acc);
    }
#undef O_ISSUE

    cp_wait<0>();
    __syncthreads();
    float* Cs = smf;
    const int gq = l >> 2, tq = l & 3;
#pragma unroll
    for (int inf = 0; inf < 2; inf++) {
        int nn = nb + inf * 16 + gq;
#pragma unroll
        for (int jm = 0; jm < 8; jm++) {
            int mm = mb + jm * 8 + 2 * tq;
            Cs[mm * 132 + nn]           = acc[inf][jm][0];
            Cs[(mm + 1) * 132 + nn]     = acc[inf][jm][1];
            Cs[mm * 132 + nn + 8]       = acc[inf][jm][2];
            Cs[(mm + 1) * 132 + nn + 8] = acc[inf][jm][3];
        }
    }
    __syncthreads();
#pragma unroll
    for (int it = 0; it < 16; it++) {
        int idx = tid + it * 256;
        int r = idx >> 5, c = (idx & 31) * 4;
        float4 v = *(float4*)&Cs[r * 132 + c];
        v.x += bias[n0 + c];
        v.y += bias[n0 + c + 1];
        v.z += bias[n0 + c + 2];
        v.w += bias[n0 + c + 3];
        *(float4*)&Cext[(size_t)(m0 + r) * ldN + n0 + c] = v;
    }
}

// ---------------- attention: 8 lanes per (b,h), 4 per warp ----------------
__global__ __launch_bounds__(256) void attn_kernel()
{
    const int wid = threadIdx.x >> 5;
    const int lane = threadIdx.x & 31;
    const int grp = lane >> 3;       // 0..3
    const int g   = lane & 7;        // 0..7
    const int bh  = (blockIdx.x * 8 + wid) * 4 + grp;
    const int b = bh >> 3, h = bh & 7;

    const __half* qb  = g_Qh  + (size_t)b * SEQ * DIM       + h * 64 + g * 8;
    const __half* kvb = g_KVh + (size_t)b * SEQ * (2 * DIM) + h * 64 + g * 8;

    uint4 kh[4], vh[4];
    float qf[4][8];
#pragma unroll
    for (int i = 0; i < 4; i++) {
        uint4 qh = __ldcs((const uint4*)&qb[i * DIM]);
        kh[i] = __ldcs((const uint4*)&kvb[i * (2 * DIM)]);
        vh[i] = __ldcs((const uint4*)&kvb[i * (2 * DIM) + DIM]);
        cvt8(qh, qf[i]);
    }

    float s[4][4];
#pragma unroll
    for (int j = 0; j < 4; j++) {
        float kf[8];
        cvt8(kh[j], kf);
#pragma unroll
        for (int i = 0; i < 4; i++) {
            float a = qf[i][0] * kf[0];
#pragma unroll
            for (int d = 1; d < 8; d++) a = fmaf(qf[i][d], kf[d], a);
            s[i][j] = a;
        }
    }
#pragma unroll
    for (int i = 0; i < 4; i++)
#pragma unroll
        for (int j = 0; j < 4; j++)
#pragma unroll
            for (int o = 4; o > 0; o >>= 1)
                s[i][j] += __shfl_xor_sync(0xFFFFFFFFu, s[i][j], o);

    float p[4][4];
#pragma unroll
    for (int i = 0; i < 4; i++) {
        const int jm = 3 - i;                       // masked pair (dist = sqrt2)
#pragma unroll
        for (int j = 0; j < 4; j++) s[i][j] *= SCALE_F;
        s[i][jm] = -(float)(jm + 1) * GAMMA_F;      // finite bias, in denominator

        float mx = fmaxf(fmaxf(s[i][0], s[i][1]), fmaxf(s[i][2], s[i][3]));
        float e0 = __expf(s[i][0] - mx), e1 = __expf(s[i][1] - mx);
        float e2 = __expf(s[i][2] - mx), e3 = __expf(s[i][3] - mx);
        float inv = 1.0f / (e0 + e1 + e2 + e3);
        p[i][0] = e0 * inv; p[i][1] = e1 * inv;
        p[i][2] = e2 * inv; p[i][3] = e3 * inv;
        p[i][jm] = 0.0f;                            // post-softmax mask
    }

    float of[4][8];
#pragma unroll
    for (int i = 0; i < 4; i++)
#pragma unroll
        for (int d = 0; d < 8; d++) of[i][d] = 0.0f;
#pragma unroll
    for (int j = 0; j < 4; j++) {
        float vf[8];
        cvt8(vh[j], vf);
#pragma unroll
        for (int i = 0; i < 4; i++)
#pragma unroll
            for (int d = 0; d < 8; d++)
                of[i][d] = fmaf(p[i][j], vf[d], of[i][d]);
    }

    __half* dst = g_AOh + (size_t)b * SEQ * DIM + h * 64 + g * 8;
#pragma unroll
    for (int i = 0; i < 4; i++) {
        __half2 hh[4];
        hh[0] = __floats2half2_rn(of[i][0], of[i][1]);
        hh[1] = __floats2half2_rn(of[i][2], of[i][3]);
        hh[2] = __floats2half2_rn(of[i][4], of[i][5]);
        hh[3] = __floats2half2_rn(of[i][6], of[i][7]);
        *(uint4*)&dst[i * DIM] = *(uint4*)hh;
    }
}

// ---------------- launch ----------------
extern "C" void kernel_launch(void* const* d_in, const int* in_sizes, int n_in,
                              void* d_out, int out_size)
{
    const float* x   = (const float*)d_in[0];
    const float* ctx = (const float*)d_in[1];
    const float* Wq  = (const float*)d_in[2];
    const float* bq  = (const float*)d_in[3];
    const float* Wkv = (const float*)d_in[4];
    const float* bkv = (const float*)d_in[5];
    const float* Wo  = (const float*)d_in[6];
    const float* bo  = (const float*)d_in[7];
    float* out = (float*)d_out;

    cudaFuncSetAttribute(gemm_qkv, cudaFuncAttributeMaxDynamicSharedMemorySize, SMEM_BYTES);
    cudaFuncSetAttribute(gemm_o, cudaFuncAttributeMaxDynamicSharedMemorySize, SMEM_BYTES);

    // prep: weight transpose + both activation conversions in ONE launch
    prep_all<<<PREP_TRANSPOSE_BLOCKS + 2 * TOH_BLOCKS, 256>>>(Wq, Wkv, Wo, x, ctx);

    // Q and KV in one launch (fp16 in/out)
    gemm_qkv<<<dim3(12, ROWS / BM), 256, SMEM_BYTES>>>(bq, bkv);
    // attention: 32 (b,h) per block -> 4096 blocks
    attn_kernel<<<BATCH * HEADS / 32, 256>>>();
    // out = AO @ Wo + bo (fp32 out)
    gemm_o<<<dim3(DIM / BN, ROWS / BM), 256, SMEM_BYTES>>>(bo, out, DIM);
}